// round 12
// baseline (speedup 1.0000x reference)
#include <cuda_runtime.h>
#include <cuda_bf16.h>
#include <math.h>

#define BB 4
#define CC 256
#define LL 4096
#define EE 8
#define DI 512
#define DS 16
#define DR 16
#define NSEG 32
#define SLOT_MAX 34816          // 32768 + 32 segs padded to 64
#define NT64 (SLOT_MAX/64)      // 544
#define NT16 (SLOT_MAX/16)      // 2176
#define RBLK 2048               // router blocks (8 tokens each)

// ---------------- scratch (static device memory; no allocations) -------------
__device__ float g_xn[(size_t)BB*LL*CC];
__device__ __nv_bfloat16 g_xn_bf[(size_t)BB*LL*CC];
__device__ __nv_bfloat16 g_win_bf[(size_t)EE*1024*CC];
__device__ __nv_bfloat16 g_wout_bf[(size_t)EE*CC*DI];
__device__ float g_probs[(size_t)BB*LL*EE];
__device__ unsigned char g_mask[(size_t)BB*LL*EE];
__device__ int   g_segcnt[NSEG];
__device__ int   g_segoff[NSEG+1];
__device__ int   g_slot_l[SLOT_MAX];
__device__ unsigned char g_slot_seg[SLOT_MAX];
__device__ unsigned char g_slot_rank[SLOT_MAX];
__device__ float g_slot_gate[SLOT_MAX];
__device__ float g_xraw[(size_t)SLOT_MAX*DI];
__device__ float g_zs  [(size_t)SLOT_MAX*DI];
__device__ float g_xi  [(size_t)SLOT_MAX*DI];
__device__ float g_dt  [(size_t)SLOT_MAX*DI];
__device__ float g_Bm  [(size_t)SLOT_MAX*DS];
__device__ float g_Cm  [(size_t)SLOT_MAX*DS];
__device__ __nv_bfloat16 g_yz_bf[(size_t)SLOT_MAX*DI];
__device__ float g_ymm [2][(size_t)BB*LL*CC];
__device__ float g_pF  [RBLK*EE];
__device__ float g_pP  [RBLK*EE];
__device__ float g_aux;

__device__ __forceinline__ void mma16816(float* c, unsigned a0, unsigned a1,
                                         unsigned a2, unsigned a3,
                                         unsigned b0, unsigned b1) {
    asm volatile(
        "mma.sync.aligned.m16n8k16.row.col.f32.bf16.bf16.f32 "
        "{%0,%1,%2,%3}, {%4,%5,%6,%7}, {%8,%9}, {%0,%1,%2,%3};"
        : "+f"(c[0]), "+f"(c[1]), "+f"(c[2]), "+f"(c[3])
        : "r"(a0), "r"(a1), "r"(a2), "r"(a3), "r"(b0), "r"(b1));
}

// ---------------- K0: weight -> bf16 conversions ------------------------------
__global__ void k_cvt(const float* __restrict__ src, __nv_bfloat16* __restrict__ dst, int n) {
    int i = blockIdx.x*256 + threadIdx.x;
    if (i < n) dst[i] = __float2bfloat16(src[i]);
}

// ---------------- K1: transpose + layernorm (writes fp32 + bf16) --------------
__global__ void k_ln(const float* __restrict__ x, const float* __restrict__ gam,
                     const float* __restrict__ bet) {
    __shared__ float sh[CC][33];
    int b  = blockIdx.x >> 7;
    int l0 = (blockIdx.x & 127) << 5;
    int tid = threadIdx.x, lane = tid & 31, w = tid >> 5;
    for (int i = 0; i < 32; i++) {
        int c = i*8 + w;
        sh[c][lane] = x[((size_t)b*CC + c)*LL + l0 + lane];
    }
    __syncthreads();
    for (int j = 0; j < 4; j++) {
        int ll = w + j*8;
        float s = 0.f, s2 = 0.f;
        for (int i = 0; i < 8; i++) {
            float v = sh[lane + i*32][ll];
            s += v; s2 += v*v;
        }
        for (int o = 16; o; o >>= 1) {
            s  += __shfl_xor_sync(~0u, s, o);
            s2 += __shfl_xor_sync(~0u, s2, o);
        }
        float mu = s * (1.f/CC);
        float var = s2 * (1.f/CC) - mu*mu;
        float rstd = rsqrtf(var + 1e-5f);
        size_t base = ((size_t)b*LL + l0 + ll) * CC;
        for (int i = 0; i < 8; i++) {
            int c = lane + i*32;
            float v = (sh[c][ll] - mu) * rstd * gam[c] + bet[c];
            g_xn[base + c] = v;
            g_xn_bf[base + c] = __float2bfloat16(v);
        }
    }
}

// ---------------- K2: router (softmax + top-2) -------------------------------
__global__ void k_router(const float* __restrict__ Wg) {
    int tid = threadIdx.x, lane = tid & 31, w = tid >> 5;
    int tok = blockIdx.x*8 + w;
    const float* xr = g_xn + (size_t)tok*CC;
    float lg[EE];
#pragma unroll
    for (int e = 0; e < EE; e++) lg[e] = 0.f;
    for (int i = 0; i < 8; i++) {
        float v = xr[lane + i*32];
        const float* wr = Wg + (size_t)(lane + i*32)*EE;
#pragma unroll
        for (int e = 0; e < EE; e++) lg[e] += v * wr[e];
    }
#pragma unroll
    for (int e = 0; e < EE; e++)
        for (int o = 16; o; o >>= 1) lg[e] += __shfl_xor_sync(~0u, lg[e], o);

    __shared__ float sp[8][EE];
    __shared__ unsigned char sm[8][EE];
    if (lane == 0) {
        float mx = lg[0];
        for (int e = 1; e < EE; e++) mx = fmaxf(mx, lg[e]);
        float pe[EE]; float se = 0.f;
        for (int e = 0; e < EE; e++) { pe[e] = expf(lg[e]-mx); se += pe[e]; }
        float inv = 1.f/se;
        int e0 = 0; float b0 = -1.f;
        for (int e = 0; e < EE; e++) { pe[e] *= inv; if (pe[e] > b0) { b0 = pe[e]; e0 = e; } }
        int e1 = 0; float b1 = -1.f;
        for (int e = 0; e < EE; e++) { if (e != e0 && pe[e] > b1) { b1 = pe[e]; e1 = e; } }
        for (int e = 0; e < EE; e++) {
            g_probs[(size_t)tok*EE + e] = pe[e];
            unsigned char m = (e == e0 || e == e1) ? 1 : 0;
            g_mask[(size_t)tok*EE + e] = m;
            sp[w][e] = pe[e]; sm[w][e] = m;
        }
    }
    __syncthreads();
    if (tid < EE) {
        float fs = 0.f, ps = 0.f;
        for (int t = 0; t < 8; t++) { fs += (float)sm[t][tid]; ps += sp[t][tid]; }
        g_pF[blockIdx.x*EE + tid] = fs;
        g_pP[blockIdx.x*EE + tid] = ps;
    }
}

// ---------------- K3: aux loss (deterministic two-pass) -----------------------
__global__ void k_aux() {
    __shared__ float sF[EE], sP[EE];
    int e = threadIdx.x;
    if (e < EE) {
        float f = 0.f, p = 0.f;
        for (int i = 0; i < RBLK; i++) { f += g_pF[i*EE+e]; p += g_pP[i*EE+e]; }
        sF[e] = f; sP[e] = p;
    }
    __syncthreads();
    if (threadIdx.x == 0) {
        float a = 0.f;
        const float nf = 1.f / ((float)BB*LL*2.f);
        const float np = 1.f / ((float)BB*LL);
        for (int k = 0; k < EE; k++) a += (sF[k]*nf) * (sP[k]*np);
        g_aux = (float)EE * a;
    }
}

// ---------------- K4: counts / offsets / init / stable compaction ------------
__global__ void k_count() {
    int seg = blockIdx.x, b = seg >> 3, e = seg & 7;
    int tid = threadIdx.x;
    int cnt = 0;
    for (int i = tid; i < LL; i += 256) cnt += g_mask[((size_t)b*LL + i)*EE + e];
    __shared__ int sc[256];
    sc[tid] = cnt; __syncthreads();
    for (int o = 128; o; o >>= 1) { if (tid < o) sc[tid] += sc[tid+o]; __syncthreads(); }
    if (tid == 0) g_segcnt[seg] = sc[0];
}

__global__ void k_off() {
    if (threadIdx.x == 0) {
        int o = 0;
        for (int s = 0; s < NSEG; s++) { g_segoff[s] = o; o += ((g_segcnt[s]+63) >> 6) << 6; }
        g_segoff[NSEG] = o;
    }
}

__global__ void k_initslot() {
    int g = blockIdx.x*256 + threadIdx.x;
    if (g < SLOT_MAX) {
        g_slot_seg[g] = 0xFF; g_slot_l[g] = 0; g_slot_gate[g] = 0.f; g_slot_rank[g] = 0;
    }
}

__global__ void k_compact() {
    int seg = blockIdx.x, b = seg >> 3, e = seg & 7;
    int tid = threadIdx.x;
    int base_l = tid*16;
    unsigned char ml[16];
    int cnt = 0;
    for (int i = 0; i < 16; i++) {
        ml[i] = g_mask[((size_t)b*LL + base_l + i)*EE + e];
        cnt += ml[i];
    }
    __shared__ int sc[256];
    sc[tid] = cnt; __syncthreads();
    for (int o = 1; o < 256; o <<= 1) {
        int v = (tid >= o) ? sc[tid-o] : 0;
        __syncthreads();
        sc[tid] += v;
        __syncthreads();
    }
    int pos = g_segoff[seg] + sc[tid] - cnt;
    for (int i = 0; i < 16; i++) {
        if (ml[i]) {
            int l = base_l + i;
            g_slot_l[pos] = l;
            g_slot_seg[pos] = (unsigned char)seg;
            g_slot_gate[pos] = g_probs[((size_t)b*LL + l)*EE + e];
            int rk = 0;
            for (int ee = 0; ee < e; ee++) rk += g_mask[((size_t)b*LL + l)*EE + ee];
            g_slot_rank[pos] = (unsigned char)rk;
            pos++;
        }
    }
}

// ---------------- K5: in-projection via bf16 tensor cores ---------------------
// D[64 x 128] per CTA: xz = xn @ W_in^T. blockIdx.y in 0..7 (8*128 = 1024 outs)
__global__ void k_gemm_in_mma() {
    __shared__ __align__(16) __nv_bfloat16 sA[64][72];
    __shared__ __align__(16) __nv_bfloat16 sB[128][72];
    __shared__ int rl[64];
    __shared__ unsigned char rv[64];
    int g0 = blockIdx.x*64;
    unsigned char seg = g_slot_seg[g0];
    if (seg == 0xFF) return;
    int e = seg & 7, b = seg >> 3;
    int tid = threadIdx.x, lane = tid & 31, wid = tid >> 5;
    int wm = wid & 1, wn = wid >> 1;
    int g = lane >> 2, tg = lane & 3;
    if (tid < 64) {
        unsigned char s2 = g_slot_seg[g0+tid];
        rv[tid] = (s2 == seg);
        rl[tid] = (s2 == seg) ? g_slot_l[g0+tid] : 0;
    }
    __syncthreads();
    float acc[2][4][4] = {};
    const __nv_bfloat16* Wb = g_win_bf + ((size_t)e*1024 + (size_t)blockIdx.y*128)*CC;
    for (int kt = 0; kt < 4; kt++) {
        int k0 = kt*64;
#pragma unroll
        for (int i = 0; i < 2; i++) {
            int lin = tid + i*256; int r = lin >> 3, q = lin & 7;
            *(float4*)&sA[r][q*8] = *(const float4*)&g_xn_bf[((size_t)b*LL + rl[r])*CC + k0 + q*8];
        }
#pragma unroll
        for (int i = 0; i < 4; i++) {
            int lin = tid + i*256; int n = lin >> 3, q = lin & 7;
            *(float4*)&sB[n][q*8] = *(const float4*)&Wb[(size_t)n*CC + k0 + q*8];
        }
        __syncthreads();
#pragma unroll
        for (int kk = 0; kk < 4; kk++) {
            int kb = kk*16 + tg*2;
            unsigned a[2][4], bf[4][2];
#pragma unroll
            for (int mt = 0; mt < 2; mt++) {
                int m = wm*32 + mt*16 + g;
                a[mt][0] = *(const unsigned*)&sA[m][kb];
                a[mt][1] = *(const unsigned*)&sA[m+8][kb];
                a[mt][2] = *(const unsigned*)&sA[m][kb+8];
                a[mt][3] = *(const unsigned*)&sA[m+8][kb+8];
            }
#pragma unroll
            for (int nt = 0; nt < 4; nt++) {
                int n = wn*32 + nt*8 + g;
                bf[nt][0] = *(const unsigned*)&sB[n][kb];
                bf[nt][1] = *(const unsigned*)&sB[n][kb+8];
            }
#pragma unroll
            for (int mt = 0; mt < 2; mt++)
#pragma unroll
                for (int nt = 0; nt < 4; nt++)
                    mma16816(acc[mt][nt], a[mt][0], a[mt][1], a[mt][2], a[mt][3],
                             bf[nt][0], bf[nt][1]);
        }
        __syncthreads();
    }
    int oBase = blockIdx.y*128 + wn*32;
#pragma unroll
    for (int mt = 0; mt < 2; mt++) {
#pragma unroll
        for (int h = 0; h < 2; h++) {
            int r = wm*32 + mt*16 + h*8 + g;
            if (!rv[r]) continue;
            size_t rowb = (size_t)(g0+r)*DI;
#pragma unroll
            for (int nt = 0; nt < 4; nt++) {
                int o = oBase + nt*8 + tg*2;
                float v0 = acc[mt][nt][h*2+0], v1 = acc[mt][nt][h*2+1];
                if (blockIdx.y < 4) {
                    *(float2*)&g_xraw[rowb + o] = make_float2(v0, v1);
                } else {
                    v0 = v0/(1.f + __expf(-v0));
                    v1 = v1/(1.f + __expf(-v1));
                    *(float2*)&g_zs[rowb + (o-512)] = make_float2(v0, v1);
                }
            }
        }
    }
}

// ---------------- K6: conv+silu, x-proj (dbc), dt ----------------------------
__global__ void k_prep(const float* __restrict__ conv_w, const float* __restrict__ conv_b,
                       const float* __restrict__ W_x, const float* __restrict__ W_dt,
                       const float* __restrict__ dt_bias) {
    __shared__ float sXI[16][DI];
    __shared__ float sDBC[16][48];
    __shared__ int nvs;
    int g0 = blockIdx.x*16;
    unsigned char seg = g_slot_seg[g0];
    if (seg == 0xFF) return;
    int e = seg & 7;
    int tid = threadIdx.x, lane = tid & 31, w = tid >> 5;
    int off = g_segoff[seg];
    if (tid == 0) {
        int nv = 0;
        for (int r = 0; r < 16; r++) if (g_slot_seg[g0+r] == seg) nv++;
        nvs = nv;
    }
    __syncthreads();
    int nv = nvs;
    for (int r = 0; r < nv; r++) {
        int g = g0 + r;
        int p = g - off;
        for (int ci = 0; ci < 2; ci++) {
            int c = tid + ci*256;
            const float* cw = conv_w + ((size_t)e*DI + c)*4;
            float acc = conv_b[(size_t)e*DI + c];
            if (p >= 3) acc += cw[0] * g_xraw[(size_t)(g-3)*DI + c];
            if (p >= 2) acc += cw[1] * g_xraw[(size_t)(g-2)*DI + c];
            if (p >= 1) acc += cw[2] * g_xraw[(size_t)(g-1)*DI + c];
            acc += cw[3] * g_xraw[(size_t)g*DI + c];
            float sg = 1.f/(1.f + __expf(-acc));
            float xi = acc*sg;
            sXI[r][c] = xi;
            g_xi[(size_t)g*DI + c] = xi;
        }
    }
    __syncthreads();
    for (int rr = 0; rr < 6; rr++) {
        int r48 = w + rr*8;
        const float* wx = W_x + ((size_t)e*48 + r48)*DI;
        float wreg[16];
#pragma unroll
        for (int i = 0; i < 16; i++) wreg[i] = wx[lane + i*32];
        for (int t = 0; t < nv; t++) {
            float a = 0.f;
#pragma unroll
            for (int i = 0; i < 16; i++) a += wreg[i] * sXI[t][lane + i*32];
            for (int o = 16; o; o >>= 1) a += __shfl_xor_sync(~0u, a, o);
            if (lane == 0) sDBC[t][r48] = a;
        }
    }
    __syncthreads();
    for (int ci = 0; ci < 2; ci++) {
        int c = tid + ci*256;
        const float* wd = W_dt + ((size_t)e*DI + c)*DR;
        float wreg[16];
#pragma unroll
        for (int i = 0; i < 16; i++) wreg[i] = wd[i];
        float bias = dt_bias[(size_t)e*DI + c];
        for (int t = 0; t < nv; t++) {
            float pre = bias;
#pragma unroll
            for (int i = 0; i < 16; i++) pre += wreg[i] * sDBC[t][i];
            float dt = (pre > 20.f) ? pre : log1pf(expf(pre));
            g_dt[(size_t)(g0+t)*DI + c] = dt;
        }
    }
    if (tid < 256) {
        int t = tid >> 4, s = tid & 15;
        if (t < nv) {
            g_Bm[(size_t)(g0+t)*DS + s] = sDBC[t][16+s];
            g_Cm[(size_t)(g0+t)*DS + s] = sDBC[t][32+s];
        }
    }
}

// ---------------- K7: sequential selective scan, channels split over y -------
__global__ void k_scan(const float* __restrict__ A_log, const float* __restrict__ Dp) {
    int seg = blockIdx.x, e = seg & 7;
    int n = g_segcnt[seg];
    if (n == 0) return;
    int g0 = g_segoff[seg];
    int tid = threadIdx.x;
    int c = blockIdx.y*128 + tid;
    float A[DS], h[DS];
#pragma unroll
    for (int s = 0; s < DS; s++) {
        A[s] = -expf(A_log[((size_t)e*DI + c)*DS + s]);
        h[s] = 0.f;
    }
    bool structured = true;
#pragma unroll
    for (int s = 1; s < DS; s++)
        structured = structured && (fabsf(A[s] - (float)(s+1)*A[0]) <= 1e-4f*fabsf(A[s]));
    float A0 = A[0];
    float dp = Dp[(size_t)e*DI + c];
    __shared__ float sB[2][DS], sC[2][DS];
    if (tid < DS)            sB[0][tid]     = g_Bm[(size_t)g0*DS + tid];
    else if (tid < 2*DS)     sC[0][tid-DS]  = g_Cm[(size_t)g0*DS + (tid-DS)];
    float dt = g_dt[(size_t)g0*DI + c];
    float xi = g_xi[(size_t)g0*DI + c];
    float zz = g_zs[(size_t)g0*DI + c];
    for (int t = 0; t < n; t++) {
        __syncthreads();
        int buf = t & 1;
        float ndt = dt, nxi = xi, nzz = zz;
        if (t+1 < n) {
            if (tid < DS)        sB[buf^1][tid]    = g_Bm[(size_t)(g0+t+1)*DS + tid];
            else if (tid < 2*DS) sC[buf^1][tid-DS] = g_Cm[(size_t)(g0+t+1)*DS + (tid-DS)];
            size_t gi2 = (size_t)(g0+t+1)*DI + c;
            ndt = g_dt[gi2]; nxi = g_xi[gi2]; nzz = g_zs[gi2];
        }
        float u = dt*xi;
        float y = dp*xi;
        if (structured) {
            float r = __expf(dt*A0);
            float p = r;
#pragma unroll
            for (int s = 0; s < DS; s++) {
                h[s] = p*h[s] + u*sB[buf][s];
                y += h[s]*sC[buf][s];
                p *= r;
            }
        } else {
#pragma unroll
            for (int s = 0; s < DS; s++) {
                float dA = __expf(dt*A[s]);
                h[s] = dA*h[s] + u*sB[buf][s];
                y += h[s]*sC[buf][s];
            }
        }
        g_yz_bf[(size_t)(g0+t)*DI + c] = __float2bfloat16(y * zz);
        dt = ndt; xi = nxi; zz = nzz;
    }
}

// ---------------- K8: out-projection via bf16 tensor cores + rank scatter ----
__global__ void k_gemm_out_mma() {
    __shared__ __align__(16) __nv_bfloat16 sA[64][72];
    __shared__ __align__(16) __nv_bfloat16 sB[128][72];
    __shared__ int rl[64];
    __shared__ unsigned char rv[64], rr[64];
    __shared__ float rg[64];
    int g0 = blockIdx.x*64;
    unsigned char seg = g_slot_seg[g0];
    if (seg == 0xFF) return;
    int e = seg & 7, b = seg >> 3;
    int tid = threadIdx.x, lane = tid & 31, wid = tid >> 5;
    int wm = wid & 1, wn = wid >> 1;
    int g = lane >> 2, tg = lane & 3;
    if (tid < 64) {
        unsigned char s2 = g_slot_seg[g0+tid];
        rv[tid] = (s2 == seg);
        rl[tid] = g_slot_l[g0+tid];
        rg[tid] = g_slot_gate[g0+tid];
        rr[tid] = g_slot_rank[g0+tid];
    }
    __syncthreads();
    float acc[2][4][4] = {};
    const __nv_bfloat16* Wb = g_wout_bf + ((size_t)e*CC + (size_t)blockIdx.y*128)*DI;
    for (int kt = 0; kt < 8; kt++) {
        int k0 = kt*64;
#pragma unroll
        for (int i = 0; i < 2; i++) {
            int lin = tid + i*256; int r = lin >> 3, q = lin & 7;
            *(float4*)&sA[r][q*8] = *(const float4*)&g_yz_bf[(size_t)(g0+r)*DI + k0 + q*8];
        }
#pragma unroll
        for (int i = 0; i < 4; i++) {
            int lin = tid + i*256; int n = lin >> 3, q = lin & 7;
            *(float4*)&sB[n][q*8] = *(const float4*)&Wb[(size_t)n*DI + k0 + q*8];
        }
        __syncthreads();
#pragma unroll
        for (int kk = 0; kk < 4; kk++) {
            int kb = kk*16 + tg*2;
            unsigned a[2][4], bf[4][2];
#pragma unroll
            for (int mt = 0; mt < 2; mt++) {
                int m = wm*32 + mt*16 + g;
                a[mt][0] = *(const unsigned*)&sA[m][kb];
                a[mt][1] = *(const unsigned*)&sA[m+8][kb];
                a[mt][2] = *(const unsigned*)&sA[m][kb+8];
                a[mt][3] = *(const unsigned*)&sA[m+8][kb+8];
            }
#pragma unroll
            for (int nt = 0; nt < 4; nt++) {
                int n = wn*32 + nt*8 + g;
                bf[nt][0] = *(const unsigned*)&sB[n][kb];
                bf[nt][1] = *(const unsigned*)&sB[n][kb+8];
            }
#pragma unroll
            for (int mt = 0; mt < 2; mt++)
#pragma unroll
                for (int nt = 0; nt < 4; nt++)
                    mma16816(acc[mt][nt], a[mt][0], a[mt][1], a[mt][2], a[mt][3],
                             bf[nt][0], bf[nt][1]);
        }
        __syncthreads();
    }
    int oBase = blockIdx.y*128 + wn*32;
#pragma unroll
    for (int mt = 0; mt < 2; mt++) {
#pragma unroll
        for (int h = 0; h < 2; h++) {
            int r = wm*32 + mt*16 + h*8 + g;
            if (!rv[r]) continue;
            float gt = rg[r];
            size_t base = ((size_t)rr[r]*BB*LL + (size_t)b*LL + rl[r])*CC;
#pragma unroll
            for (int nt = 0; nt < 4; nt++) {
                int o = oBase + nt*8 + tg*2;
                *(float2*)&g_ymm[0][base + o] =
                    make_float2(gt*acc[mt][nt][h*2+0], gt*acc[mt][nt][h*2+1]);
            }
        }
    }
}

// ---------------- K9: residual + transpose back + aux ------------------------
__global__ void k_final(const float* __restrict__ x, const float* __restrict__ gamma,
                        float* __restrict__ out, int out_size) {
    __shared__ float sh[32][CC+1];
    int b  = blockIdx.x >> 7;
    int l0 = (blockIdx.x & 127) << 5;
    int tid = threadIdx.x;
    for (int i = 0; i < 32; i++) {
        size_t idx = ((size_t)b*LL + l0 + i)*CC + tid;
        sh[i][tid] = g_ymm[0][idx] + g_ymm[1][idx];
    }
    __syncthreads();
    int ll = tid & 31, cg = tid >> 5;
    for (int i = 0; i < 32; i++) {
        int c = cg*32 + i;
        size_t idx = ((size_t)b*CC + c)*LL + l0 + ll;
        out[idx] = x[idx] + gamma[c]*sh[ll][c];
    }
    if (blockIdx.x == 0 && tid == 0 && out_size > BB*CC*LL)
        out[BB*CC*LL] = g_aux;
}

// ---------------- launch ------------------------------------------------------
extern "C" void kernel_launch(void* const* d_in, const int* in_sizes, int n_in,
                              void* d_out, int out_size) {
    const float* x       = (const float*)d_in[0];
    const float* ln_g    = (const float*)d_in[1];
    const float* ln_b    = (const float*)d_in[2];
    const float* gamma   = (const float*)d_in[3];
    const float* Wg      = (const float*)d_in[4];
    const float* W_in    = (const float*)d_in[5];
    const float* conv_w  = (const float*)d_in[6];
    const float* conv_b  = (const float*)d_in[7];
    const float* W_x     = (const float*)d_in[8];
    const float* W_dt    = (const float*)d_in[9];
    const float* dt_bias = (const float*)d_in[10];
    const float* A_log   = (const float*)d_in[11];
    const float* Dp      = (const float*)d_in[12];
    const float* W_out   = (const float*)d_in[13];
    float* out = (float*)d_out;

    __nv_bfloat16* winbf;  cudaGetSymbolAddress((void**)&winbf,  g_win_bf);
    __nv_bfloat16* woutbf; cudaGetSymbolAddress((void**)&woutbf, g_wout_bf);

    k_cvt<<<(EE*1024*CC+255)/256, 256>>>(W_in,  winbf,  EE*1024*CC);
    k_cvt<<<(EE*CC*DI+255)/256, 256>>>(W_out, woutbf, EE*CC*DI);
    k_ln<<<BB*(LL/32), 256>>>(x, ln_g, ln_b);
    k_router<<<RBLK, 256>>>(Wg);
    k_aux<<<1, 32>>>();
    k_count<<<NSEG, 256>>>();
    k_off<<<1, 32>>>();
    k_initslot<<<(SLOT_MAX+255)/256, 256>>>();
    k_compact<<<NSEG, 256>>>();
    k_gemm_in_mma<<<dim3(NT64, 8), 256>>>();
    k_prep<<<NT16, 256>>>(conv_w, conv_b, W_x, W_dt, dt_bias);
    k_scan<<<dim3(NSEG, 4), 128>>>(A_log, Dp);
    k_gemm_out_mma<<<dim3(NT64, 2), 256>>>();
    k_final<<<BB*(LL/32), 256>>>(x, gamma, out, out_size);
}

// round 13
// speedup vs baseline: 1.0020x; 1.0020x over previous
#include <cuda_runtime.h>
#include <cuda_bf16.h>
#include <math.h>

#define BB 4
#define CC 256
#define LL 4096
#define EE 8
#define DI 512
#define DS 16
#define DR 16
#define NSEG 32
#define SLOT_MAX 34816          // 32768 + 32 segs padded to 64
#define NT64 (SLOT_MAX/64)      // 544
#define NT16 (SLOT_MAX/16)      // 2176
#define RBLK 2048               // router blocks (8 tokens each)

// ---------------- scratch (static device memory; no allocations) -------------
__device__ float g_xn[(size_t)BB*LL*CC];
__device__ __nv_bfloat16 g_xn_bf[(size_t)BB*LL*CC];
__device__ __nv_bfloat16 g_win_bf[(size_t)EE*1024*CC];
__device__ __nv_bfloat16 g_wout_bf[(size_t)EE*CC*DI];
__device__ float g_probs[(size_t)BB*LL*EE];
__device__ unsigned char g_mask[(size_t)BB*LL*EE];
__device__ int   g_segcnt[NSEG];
__device__ int   g_segoff[NSEG+1];
__device__ int   g_slot_l[SLOT_MAX];
__device__ unsigned char g_slot_seg[SLOT_MAX];
__device__ unsigned char g_slot_rank[SLOT_MAX];
__device__ float g_slot_gate[SLOT_MAX];
__device__ float g_xraw[(size_t)SLOT_MAX*DI];
__device__ float g_zs  [(size_t)SLOT_MAX*DI];
__device__ float g_xi  [(size_t)SLOT_MAX*DI];
__device__ float g_dt  [(size_t)SLOT_MAX*DI];
__device__ float g_Bm  [(size_t)SLOT_MAX*DS];
__device__ float g_Cm  [(size_t)SLOT_MAX*DS];
__device__ __nv_bfloat16 g_yz_bf[(size_t)SLOT_MAX*DI];
__device__ float g_ymm [2][(size_t)BB*LL*CC];
__device__ float g_pF  [RBLK*EE];
__device__ float g_pP  [RBLK*EE];
__device__ float g_aux;

__device__ __forceinline__ void mma16816(float* c, unsigned a0, unsigned a1,
                                         unsigned a2, unsigned a3,
                                         unsigned b0, unsigned b1) {
    asm volatile(
        "mma.sync.aligned.m16n8k16.row.col.f32.bf16.bf16.f32 "
        "{%0,%1,%2,%3}, {%4,%5,%6,%7}, {%8,%9}, {%0,%1,%2,%3};"
        : "+f"(c[0]), "+f"(c[1]), "+f"(c[2]), "+f"(c[3])
        : "r"(a0), "r"(a1), "r"(a2), "r"(a3), "r"(b0), "r"(b1));
}

// ---------------- K0: weight -> bf16 conversions ------------------------------
__global__ void k_cvt(const float* __restrict__ src, __nv_bfloat16* __restrict__ dst, int n) {
    int i = blockIdx.x*256 + threadIdx.x;
    if (i < n) dst[i] = __float2bfloat16(src[i]);
}

// ---------------- K1: transpose + layernorm (writes fp32 + bf16) --------------
__global__ void k_ln(const float* __restrict__ x, const float* __restrict__ gam,
                     const float* __restrict__ bet) {
    __shared__ float sh[CC][33];
    int b  = blockIdx.x >> 7;
    int l0 = (blockIdx.x & 127) << 5;
    int tid = threadIdx.x, lane = tid & 31, w = tid >> 5;
    for (int i = 0; i < 32; i++) {
        int c = i*8 + w;
        sh[c][lane] = x[((size_t)b*CC + c)*LL + l0 + lane];
    }
    __syncthreads();
    for (int j = 0; j < 4; j++) {
        int ll = w + j*8;
        float s = 0.f, s2 = 0.f;
        for (int i = 0; i < 8; i++) {
            float v = sh[lane + i*32][ll];
            s += v; s2 += v*v;
        }
        for (int o = 16; o; o >>= 1) {
            s  += __shfl_xor_sync(~0u, s, o);
            s2 += __shfl_xor_sync(~0u, s2, o);
        }
        float mu = s * (1.f/CC);
        float var = s2 * (1.f/CC) - mu*mu;
        float rstd = rsqrtf(var + 1e-5f);
        size_t base = ((size_t)b*LL + l0 + ll) * CC;
        for (int i = 0; i < 8; i++) {
            int c = lane + i*32;
            float v = (sh[c][ll] - mu) * rstd * gam[c] + bet[c];
            g_xn[base + c] = v;
            g_xn_bf[base + c] = __float2bfloat16(v);
        }
    }
}

// ---------------- K2: router (softmax + top-2) -------------------------------
__global__ void k_router(const float* __restrict__ Wg) {
    int tid = threadIdx.x, lane = tid & 31, w = tid >> 5;
    int tok = blockIdx.x*8 + w;
    const float* xr = g_xn + (size_t)tok*CC;
    float lg[EE];
#pragma unroll
    for (int e = 0; e < EE; e++) lg[e] = 0.f;
    for (int i = 0; i < 8; i++) {
        float v = xr[lane + i*32];
        const float* wr = Wg + (size_t)(lane + i*32)*EE;
#pragma unroll
        for (int e = 0; e < EE; e++) lg[e] += v * wr[e];
    }
#pragma unroll
    for (int e = 0; e < EE; e++)
        for (int o = 16; o; o >>= 1) lg[e] += __shfl_xor_sync(~0u, lg[e], o);

    __shared__ float sp[8][EE];
    __shared__ unsigned char sm[8][EE];
    if (lane == 0) {
        float mx = lg[0];
        for (int e = 1; e < EE; e++) mx = fmaxf(mx, lg[e]);
        float pe[EE]; float se = 0.f;
        for (int e = 0; e < EE; e++) { pe[e] = expf(lg[e]-mx); se += pe[e]; }
        float inv = 1.f/se;
        int e0 = 0; float b0 = -1.f;
        for (int e = 0; e < EE; e++) { pe[e] *= inv; if (pe[e] > b0) { b0 = pe[e]; e0 = e; } }
        int e1 = 0; float b1 = -1.f;
        for (int e = 0; e < EE; e++) { if (e != e0 && pe[e] > b1) { b1 = pe[e]; e1 = e; } }
        for (int e = 0; e < EE; e++) {
            g_probs[(size_t)tok*EE + e] = pe[e];
            unsigned char m = (e == e0 || e == e1) ? 1 : 0;
            g_mask[(size_t)tok*EE + e] = m;
            sp[w][e] = pe[e]; sm[w][e] = m;
        }
    }
    __syncthreads();
    if (tid < EE) {
        float fs = 0.f, ps = 0.f;
        for (int t = 0; t < 8; t++) { fs += (float)sm[t][tid]; ps += sp[t][tid]; }
        g_pF[blockIdx.x*EE + tid] = fs;
        g_pP[blockIdx.x*EE + tid] = ps;
    }
}

// ---------------- K3: aux loss (deterministic two-pass) -----------------------
__global__ void k_aux() {
    __shared__ float sF[EE], sP[EE];
    int e = threadIdx.x;
    if (e < EE) {
        float f = 0.f, p = 0.f;
        for (int i = 0; i < RBLK; i++) { f += g_pF[i*EE+e]; p += g_pP[i*EE+e]; }
        sF[e] = f; sP[e] = p;
    }
    __syncthreads();
    if (threadIdx.x == 0) {
        float a = 0.f;
        const float nf = 1.f / ((float)BB*LL*2.f);
        const float np = 1.f / ((float)BB*LL);
        for (int k = 0; k < EE; k++) a += (sF[k]*nf) * (sP[k]*np);
        g_aux = (float)EE * a;
    }
}

// ---------------- K4: counts / offsets / init / stable compaction ------------
__global__ void k_count() {
    int seg = blockIdx.x, b = seg >> 3, e = seg & 7;
    int tid = threadIdx.x;
    int cnt = 0;
    for (int i = tid; i < LL; i += 256) cnt += g_mask[((size_t)b*LL + i)*EE + e];
    __shared__ int sc[256];
    sc[tid] = cnt; __syncthreads();
    for (int o = 128; o; o >>= 1) { if (tid < o) sc[tid] += sc[tid+o]; __syncthreads(); }
    if (tid == 0) g_segcnt[seg] = sc[0];
}

__global__ void k_off() {
    if (threadIdx.x == 0) {
        int o = 0;
        for (int s = 0; s < NSEG; s++) { g_segoff[s] = o; o += ((g_segcnt[s]+63) >> 6) << 6; }
        g_segoff[NSEG] = o;
    }
}

__global__ void k_initslot() {
    int g = blockIdx.x*256 + threadIdx.x;
    if (g < SLOT_MAX) {
        g_slot_seg[g] = 0xFF; g_slot_l[g] = 0; g_slot_gate[g] = 0.f; g_slot_rank[g] = 0;
    }
}

__global__ void k_compact() {
    int seg = blockIdx.x, b = seg >> 3, e = seg & 7;
    int tid = threadIdx.x;
    int base_l = tid*16;
    unsigned char ml[16];
    int cnt = 0;
    for (int i = 0; i < 16; i++) {
        ml[i] = g_mask[((size_t)b*LL + base_l + i)*EE + e];
        cnt += ml[i];
    }
    __shared__ int sc[256];
    sc[tid] = cnt; __syncthreads();
    for (int o = 1; o < 256; o <<= 1) {
        int v = (tid >= o) ? sc[tid-o] : 0;
        __syncthreads();
        sc[tid] += v;
        __syncthreads();
    }
    int pos = g_segoff[seg] + sc[tid] - cnt;
    for (int i = 0; i < 16; i++) {
        if (ml[i]) {
            int l = base_l + i;
            g_slot_l[pos] = l;
            g_slot_seg[pos] = (unsigned char)seg;
            g_slot_gate[pos] = g_probs[((size_t)b*LL + l)*EE + e];
            int rk = 0;
            for (int ee = 0; ee < e; ee++) rk += g_mask[((size_t)b*LL + l)*EE + ee];
            g_slot_rank[pos] = (unsigned char)rk;
            pos++;
        }
    }
}

// ---------------- K5: in-projection via bf16 tensor cores ---------------------
// D[64 x 128] per CTA: xz = xn @ W_in^T. blockIdx.y in 0..7 (8*128 = 1024 outs)
__global__ void k_gemm_in_mma() {
    __shared__ __align__(16) __nv_bfloat16 sA[64][72];
    __shared__ __align__(16) __nv_bfloat16 sB[128][72];
    __shared__ int rl[64];
    __shared__ unsigned char rv[64];
    int g0 = blockIdx.x*64;
    unsigned char seg = g_slot_seg[g0];
    if (seg == 0xFF) return;
    int e = seg & 7, b = seg >> 3;
    int tid = threadIdx.x, lane = tid & 31, wid = tid >> 5;
    int wm = wid & 1, wn = wid >> 1;
    int g = lane >> 2, tg = lane & 3;
    if (tid < 64) {
        unsigned char s2 = g_slot_seg[g0+tid];
        rv[tid] = (s2 == seg);
        rl[tid] = (s2 == seg) ? g_slot_l[g0+tid] : 0;
    }
    __syncthreads();
    float acc[2][4][4] = {};
    const __nv_bfloat16* Wb = g_win_bf + ((size_t)e*1024 + (size_t)blockIdx.y*128)*CC;
    for (int kt = 0; kt < 4; kt++) {
        int k0 = kt*64;
#pragma unroll
        for (int i = 0; i < 2; i++) {
            int lin = tid + i*256; int r = lin >> 3, q = lin & 7;
            *(float4*)&sA[r][q*8] = *(const float4*)&g_xn_bf[((size_t)b*LL + rl[r])*CC + k0 + q*8];
        }
#pragma unroll
        for (int i = 0; i < 4; i++) {
            int lin = tid + i*256; int n = lin >> 3, q = lin & 7;
            *(float4*)&sB[n][q*8] = *(const float4*)&Wb[(size_t)n*CC + k0 + q*8];
        }
        __syncthreads();
#pragma unroll
        for (int kk = 0; kk < 4; kk++) {
            int kb = kk*16 + tg*2;
            unsigned a[2][4], bf[4][2];
#pragma unroll
            for (int mt = 0; mt < 2; mt++) {
                int m = wm*32 + mt*16 + g;
                a[mt][0] = *(const unsigned*)&sA[m][kb];
                a[mt][1] = *(const unsigned*)&sA[m+8][kb];
                a[mt][2] = *(const unsigned*)&sA[m][kb+8];
                a[mt][3] = *(const unsigned*)&sA[m+8][kb+8];
            }
#pragma unroll
            for (int nt = 0; nt < 4; nt++) {
                int n = wn*32 + nt*8 + g;
                bf[nt][0] = *(const unsigned*)&sB[n][kb];
                bf[nt][1] = *(const unsigned*)&sB[n][kb+8];
            }
#pragma unroll
            for (int mt = 0; mt < 2; mt++)
#pragma unroll
                for (int nt = 0; nt < 4; nt++)
                    mma16816(acc[mt][nt], a[mt][0], a[mt][1], a[mt][2], a[mt][3],
                             bf[nt][0], bf[nt][1]);
        }
        __syncthreads();
    }
    int oBase = blockIdx.y*128 + wn*32;
#pragma unroll
    for (int mt = 0; mt < 2; mt++) {
#pragma unroll
        for (int h = 0; h < 2; h++) {
            int r = wm*32 + mt*16 + h*8 + g;
            if (!rv[r]) continue;
            size_t rowb = (size_t)(g0+r)*DI;
#pragma unroll
            for (int nt = 0; nt < 4; nt++) {
                int o = oBase + nt*8 + tg*2;
                float v0 = acc[mt][nt][h*2+0], v1 = acc[mt][nt][h*2+1];
                if (blockIdx.y < 4) {
                    *(float2*)&g_xraw[rowb + o] = make_float2(v0, v1);
                } else {
                    v0 = v0/(1.f + __expf(-v0));
                    v1 = v1/(1.f + __expf(-v1));
                    *(float2*)&g_zs[rowb + (o-512)] = make_float2(v0, v1);
                }
            }
        }
    }
}

// ---------------- K6: conv+silu, x-proj (dbc), dt ----------------------------
__global__ void k_prep(const float* __restrict__ conv_w, const float* __restrict__ conv_b,
                       const float* __restrict__ W_x, const float* __restrict__ W_dt,
                       const float* __restrict__ dt_bias) {
    __shared__ float sXI[16][DI];
    __shared__ float sDBC[16][48];
    __shared__ int nvs;
    int g0 = blockIdx.x*16;
    unsigned char seg = g_slot_seg[g0];
    if (seg == 0xFF) return;
    int e = seg & 7;
    int tid = threadIdx.x, lane = tid & 31, w = tid >> 5;
    int off = g_segoff[seg];
    if (tid == 0) {
        int nv = 0;
        for (int r = 0; r < 16; r++) if (g_slot_seg[g0+r] == seg) nv++;
        nvs = nv;
    }
    __syncthreads();
    int nv = nvs;
    for (int r = 0; r < nv; r++) {
        int g = g0 + r;
        int p = g - off;
        for (int ci = 0; ci < 2; ci++) {
            int c = tid + ci*256;
            const float* cw = conv_w + ((size_t)e*DI + c)*4;
            float acc = conv_b[(size_t)e*DI + c];
            if (p >= 3) acc += cw[0] * g_xraw[(size_t)(g-3)*DI + c];
            if (p >= 2) acc += cw[1] * g_xraw[(size_t)(g-2)*DI + c];
            if (p >= 1) acc += cw[2] * g_xraw[(size_t)(g-1)*DI + c];
            acc += cw[3] * g_xraw[(size_t)g*DI + c];
            float sg = 1.f/(1.f + __expf(-acc));
            float xi = acc*sg;
            sXI[r][c] = xi;
            g_xi[(size_t)g*DI + c] = xi;
        }
    }
    __syncthreads();
    for (int rr = 0; rr < 6; rr++) {
        int r48 = w + rr*8;
        const float* wx = W_x + ((size_t)e*48 + r48)*DI;
        float wreg[16];
#pragma unroll
        for (int i = 0; i < 16; i++) wreg[i] = wx[lane + i*32];
        for (int t = 0; t < nv; t++) {
            float a = 0.f;
#pragma unroll
            for (int i = 0; i < 16; i++) a += wreg[i] * sXI[t][lane + i*32];
            for (int o = 16; o; o >>= 1) a += __shfl_xor_sync(~0u, a, o);
            if (lane == 0) sDBC[t][r48] = a;
        }
    }
    __syncthreads();
    for (int ci = 0; ci < 2; ci++) {
        int c = tid + ci*256;
        const float* wd = W_dt + ((size_t)e*DI + c)*DR;
        float wreg[16];
#pragma unroll
        for (int i = 0; i < 16; i++) wreg[i] = wd[i];
        float bias = dt_bias[(size_t)e*DI + c];
        for (int t = 0; t < nv; t++) {
            float pre = bias;
#pragma unroll
            for (int i = 0; i < 16; i++) pre += wreg[i] * sDBC[t][i];
            float dt = (pre > 20.f) ? pre : log1pf(expf(pre));
            g_dt[(size_t)(g0+t)*DI + c] = dt;
        }
    }
    if (tid < 256) {
        int t = tid >> 4, s = tid & 15;
        if (t < nv) {
            g_Bm[(size_t)(g0+t)*DS + s] = sDBC[t][16+s];
            g_Cm[(size_t)(g0+t)*DS + s] = sDBC[t][32+s];
        }
    }
}

// ---------------- K7: sequential selective scan, channels split over y -------
__global__ void k_scan(const float* __restrict__ A_log, const float* __restrict__ Dp) {
    int seg = blockIdx.x, e = seg & 7;
    int n = g_segcnt[seg];
    if (n == 0) return;
    int g0 = g_segoff[seg];
    int tid = threadIdx.x;
    int c = blockIdx.y*128 + tid;
    float A[DS], h[DS];
#pragma unroll
    for (int s = 0; s < DS; s++) {
        A[s] = -expf(A_log[((size_t)e*DI + c)*DS + s]);
        h[s] = 0.f;
    }
    bool structured = true;
#pragma unroll
    for (int s = 1; s < DS; s++)
        structured = structured && (fabsf(A[s] - (float)(s+1)*A[0]) <= 1e-4f*fabsf(A[s]));
    float A0 = A[0];
    float dp = Dp[(size_t)e*DI + c];
    __shared__ float sB[2][DS], sC[2][DS];
    if (tid < DS)            sB[0][tid]     = g_Bm[(size_t)g0*DS + tid];
    else if (tid < 2*DS)     sC[0][tid-DS]  = g_Cm[(size_t)g0*DS + (tid-DS)];
    float dt = g_dt[(size_t)g0*DI + c];
    float xi = g_xi[(size_t)g0*DI + c];
    float zz = g_zs[(size_t)g0*DI + c];
    for (int t = 0; t < n; t++) {
        __syncthreads();
        int buf = t & 1;
        float ndt = dt, nxi = xi, nzz = zz;
        if (t+1 < n) {
            if (tid < DS)        sB[buf^1][tid]    = g_Bm[(size_t)(g0+t+1)*DS + tid];
            else if (tid < 2*DS) sC[buf^1][tid-DS] = g_Cm[(size_t)(g0+t+1)*DS + (tid-DS)];
            size_t gi2 = (size_t)(g0+t+1)*DI + c;
            ndt = g_dt[gi2]; nxi = g_xi[gi2]; nzz = g_zs[gi2];
        }
        float u = dt*xi;
        float y = dp*xi;
        if (structured) {
            float r = __expf(dt*A0);
            float p = r;
#pragma unroll
            for (int s = 0; s < DS; s++) {
                h[s] = p*h[s] + u*sB[buf][s];
                y += h[s]*sC[buf][s];
                p *= r;
            }
        } else {
#pragma unroll
            for (int s = 0; s < DS; s++) {
                float dA = __expf(dt*A[s]);
                h[s] = dA*h[s] + u*sB[buf][s];
                y += h[s]*sC[buf][s];
            }
        }
        g_yz_bf[(size_t)(g0+t)*DI + c] = __float2bfloat16(y * zz);
        dt = ndt; xi = nxi; zz = nzz;
    }
}

// ---------------- K8: out-projection via bf16 tensor cores + rank scatter ----
__global__ void k_gemm_out_mma() {
    __shared__ __align__(16) __nv_bfloat16 sA[64][72];
    __shared__ __align__(16) __nv_bfloat16 sB[128][72];
    __shared__ int rl[64];
    __shared__ unsigned char rv[64], rr[64];
    __shared__ float rg[64];
    int g0 = blockIdx.x*64;
    unsigned char seg = g_slot_seg[g0];
    if (seg == 0xFF) return;
    int e = seg & 7, b = seg >> 3;
    int tid = threadIdx.x, lane = tid & 31, wid = tid >> 5;
    int wm = wid & 1, wn = wid >> 1;
    int g = lane >> 2, tg = lane & 3;
    if (tid < 64) {
        unsigned char s2 = g_slot_seg[g0+tid];
        rv[tid] = (s2 == seg);
        rl[tid] = g_slot_l[g0+tid];
        rg[tid] = g_slot_gate[g0+tid];
        rr[tid] = g_slot_rank[g0+tid];
    }
    __syncthreads();
    float acc[2][4][4] = {};
    const __nv_bfloat16* Wb = g_wout_bf + ((size_t)e*CC + (size_t)blockIdx.y*128)*DI;
    for (int kt = 0; kt < 8; kt++) {
        int k0 = kt*64;
#pragma unroll
        for (int i = 0; i < 2; i++) {
            int lin = tid + i*256; int r = lin >> 3, q = lin & 7;
            *(float4*)&sA[r][q*8] = *(const float4*)&g_yz_bf[(size_t)(g0+r)*DI + k0 + q*8];
        }
#pragma unroll
        for (int i = 0; i < 4; i++) {
            int lin = tid + i*256; int n = lin >> 3, q = lin & 7;
            *(float4*)&sB[n][q*8] = *(const float4*)&Wb[(size_t)n*DI + k0 + q*8];
        }
        __syncthreads();
#pragma unroll
        for (int kk = 0; kk < 4; kk++) {
            int kb = kk*16 + tg*2;
            unsigned a[2][4], bf[4][2];
#pragma unroll
            for (int mt = 0; mt < 2; mt++) {
                int m = wm*32 + mt*16 + g;
                a[mt][0] = *(const unsigned*)&sA[m][kb];
                a[mt][1] = *(const unsigned*)&sA[m+8][kb];
                a[mt][2] = *(const unsigned*)&sA[m][kb+8];
                a[mt][3] = *(const unsigned*)&sA[m+8][kb+8];
            }
#pragma unroll
            for (int nt = 0; nt < 4; nt++) {
                int n = wn*32 + nt*8 + g;
                bf[nt][0] = *(const unsigned*)&sB[n][kb];
                bf[nt][1] = *(const unsigned*)&sB[n][kb+8];
            }
#pragma unroll
            for (int mt = 0; mt < 2; mt++)
#pragma unroll
                for (int nt = 0; nt < 4; nt++)
                    mma16816(acc[mt][nt], a[mt][0], a[mt][1], a[mt][2], a[mt][3],
                             bf[nt][0], bf[nt][1]);
        }
        __syncthreads();
    }
    int oBase = blockIdx.y*128 + wn*32;
#pragma unroll
    for (int mt = 0; mt < 2; mt++) {
#pragma unroll
        for (int h = 0; h < 2; h++) {
            int r = wm*32 + mt*16 + h*8 + g;
            if (!rv[r]) continue;
            float gt = rg[r];
            size_t base = ((size_t)rr[r]*BB*LL + (size_t)b*LL + rl[r])*CC;
#pragma unroll
            for (int nt = 0; nt < 4; nt++) {
                int o = oBase + nt*8 + tg*2;
                *(float2*)&g_ymm[0][base + o] =
                    make_float2(gt*acc[mt][nt][h*2+0], gt*acc[mt][nt][h*2+1]);
            }
        }
    }
}

// ---------------- K9: residual + transpose back + aux ------------------------
__global__ void k_final(const float* __restrict__ x, const float* __restrict__ gamma,
                        float* __restrict__ out, int out_size) {
    __shared__ float sh[32][CC+1];
    int b  = blockIdx.x >> 7;
    int l0 = (blockIdx.x & 127) << 5;
    int tid = threadIdx.x;
    for (int i = 0; i < 32; i++) {
        size_t idx = ((size_t)b*LL + l0 + i)*CC + tid;
        sh[i][tid] = g_ymm[0][idx] + g_ymm[1][idx];
    }
    __syncthreads();
    int ll = tid & 31, cg = tid >> 5;
    for (int i = 0; i < 32; i++) {
        int c = cg*32 + i;
        size_t idx = ((size_t)b*CC + c)*LL + l0 + ll;
        out[idx] = x[idx] + gamma[c]*sh[ll][c];
    }
    if (blockIdx.x == 0 && tid == 0 && out_size > BB*CC*LL)
        out[BB*CC*LL] = g_aux;
}

// ---------------- launch ------------------------------------------------------
extern "C" void kernel_launch(void* const* d_in, const int* in_sizes, int n_in,
                              void* d_out, int out_size) {
    const float* x       = (const float*)d_in[0];
    const float* ln_g    = (const float*)d_in[1];
    const float* ln_b    = (const float*)d_in[2];
    const float* gamma   = (const float*)d_in[3];
    const float* Wg      = (const float*)d_in[4];
    const float* W_in    = (const float*)d_in[5];
    const float* conv_w  = (const float*)d_in[6];
    const float* conv_b  = (const float*)d_in[7];
    const float* W_x     = (const float*)d_in[8];
    const float* W_dt    = (const float*)d_in[9];
    const float* dt_bias = (const float*)d_in[10];
    const float* A_log   = (const float*)d_in[11];
    const float* Dp      = (const float*)d_in[12];
    const float* W_out   = (const float*)d_in[13];
    float* out = (float*)d_out;

    __nv_bfloat16* winbf;  cudaGetSymbolAddress((void**)&winbf,  g_win_bf);
    __nv_bfloat16* woutbf; cudaGetSymbolAddress((void**)&woutbf, g_wout_bf);

    k_cvt<<<(EE*1024*CC+255)/256, 256>>>(W_in,  winbf,  EE*1024*CC);
    k_cvt<<<(EE*CC*DI+255)/256, 256>>>(W_out, woutbf, EE*CC*DI);
    k_ln<<<BB*(LL/32), 256>>>(x, ln_g, ln_b);
    k_router<<<RBLK, 256>>>(Wg);
    k_aux<<<1, 32>>>();
    k_count<<<NSEG, 256>>>();
    k_off<<<1, 32>>>();
    k_initslot<<<(SLOT_MAX+255)/256, 256>>>();
    k_compact<<<NSEG, 256>>>();
    k_gemm_in_mma<<<dim3(NT64, 8), 256>>>();
    k_prep<<<NT16, 256>>>(conv_w, conv_b, W_x, W_dt, dt_bias);
    k_scan<<<dim3(NSEG, 4), 128>>>(A_log, Dp);
    k_gemm_out_mma<<<dim3(NT64, 2), 256>>>();
    k_final<<<BB*(LL/32), 256>>>(x, gamma, out, out_size);
}